// round 9
// baseline (speedup 1.0000x reference)
#include <cuda_runtime.h>
#include <cstdint>

#define NN   100000
#define NE   1600000
#define DH   128
#define DO   40
#define EPSB 1e-5f
#define NB_SCAN 98            // ceil(NN/1024)

// ---------------- scratch (static device globals; no allocations) ----------
__device__ float g_H  [(size_t)NN * DH];
__device__ float g_A  [(size_t)NN * DH];
__device__ float g_H40[(size_t)NN * DO];
__device__ float g_dinv[NN];
__device__ int   g_cnt [NN];
__device__ int   g_rowptr[NN + 1];
__device__ int   g_head[NN];
__device__ int   g_bsum[128];
__device__ int2  g_csr[NE];
__device__ float g_cs [DH];
__device__ float g_cs2[DH];
__device__ float g_bnsc[DH];
__device__ float g_bnsh[DH];
__device__ int   g_is64;

// ---------------- helpers ---------------------------------------------------
__device__ __forceinline__ void edge_pair(const void* ei, int e, int& s, int& d) {
    if (g_is64) {
        const long long* p = (const long long*)ei;
        s = (int)__ldg(p + e);
        d = (int)__ldg(p + NE + e);
    } else {
        const int* p = (const int*)ei;
        s = __ldg(p + e);
        d = __ldg(p + NE + e);
    }
}

// ---------------- dtype detection ------------------------------------------
__global__ void k_detect(const long long* __restrict__ p) {
    if (blockIdx.x == 0 && threadIdx.x == 0) {
        int ok = 1;
        for (int i = 0; i < 256; i++) {
            long long v = p[i];
            if (v < 0 || v >= NN) { ok = 0; break; }
        }
        g_is64 = ok;
    }
}

// ---------------- CSR build --------------------------------------------------
__global__ void k_zero() {
    int i = blockIdx.x * blockDim.x + threadIdx.x;
    if (i < NN) g_cnt[i] = 0;
    if (i < DH) { g_cs[i] = 0.f; g_cs2[i] = 0.f; }
}

__global__ void k_count(const void* __restrict__ ei) {
    int e = blockIdx.x * blockDim.x + threadIdx.x;
    if (e >= NE) return;
    int s, d;
    edge_pair(ei, e, s, d);
    atomicAdd(&g_cnt[d], 1);
}

// scan1 also computes dinv (cnt already in registers)
__global__ void k_scan1() {
    __shared__ int wsumsh[8];
    __shared__ int woff[8];
    int t = threadIdx.x, lane = t & 31, w = t >> 5;
    int base = blockIdx.x * 1024 + t * 4;
    int v0 = 0, v1 = 0, v2 = 0, v3 = 0;
    if (base + 3 < NN) {
        int4 c = *(const int4*)&g_cnt[base];
        v0 = c.x; v1 = c.y; v2 = c.z; v3 = c.w;
    } else {
        if (base     < NN) v0 = g_cnt[base];
        if (base + 1 < NN) v1 = g_cnt[base + 1];
        if (base + 2 < NN) v2 = g_cnt[base + 2];
        if (base + 3 < NN) v3 = g_cnt[base + 3];
    }
    if (base     < NN) g_dinv[base]     = rsqrtf((float)v0 + 1.0f);
    if (base + 1 < NN) g_dinv[base + 1] = rsqrtf((float)v1 + 1.0f);
    if (base + 2 < NN) g_dinv[base + 2] = rsqrtf((float)v2 + 1.0f);
    if (base + 3 < NN) g_dinv[base + 3] = rsqrtf((float)v3 + 1.0f);
    int lsum = v0 + v1 + v2 + v3;
    int x = lsum;
    #pragma unroll
    for (int o = 1; o < 32; o <<= 1) {
        int y = __shfl_up_sync(0xffffffffu, x, o);
        if (lane >= o) x += y;
    }
    if (lane == 31) wsumsh[w] = x;
    __syncthreads();
    if (t == 0) {
        int r = 0;
        for (int i = 0; i < 8; i++) { woff[i] = r; r += wsumsh[i]; }
        g_bsum[blockIdx.x] = r;
    }
    __syncthreads();
    int excl = x - lsum + woff[w];
    if (base     < NN) g_rowptr[base]     = excl;
    if (base + 1 < NN) g_rowptr[base + 1] = excl + v0;
    if (base + 2 < NN) g_rowptr[base + 2] = excl + v0 + v1;
    if (base + 3 < NN) g_rowptr[base + 3] = excl + v0 + v1 + v2;
}

__global__ void k_scan2() {
    __shared__ int sh[128];
    int t = threadIdx.x;
    sh[t] = (t < NB_SCAN) ? g_bsum[t] : 0;
    __syncthreads();
    if (t == 0) {
        int r = 0;
        for (int i = 0; i < NB_SCAN; i++) { int c = sh[i]; sh[i] = r; r += c; }
    }
    __syncthreads();
    if (t < NB_SCAN) g_bsum[t] = sh[t];
}

__global__ void k_scan3() {
    int boff = g_bsum[blockIdx.x];
    int t = threadIdx.x;
    int base = blockIdx.x * 1024 + t * 4;
    #pragma unroll
    for (int j = 0; j < 4; j++) {
        int idx = base + j;
        if (idx < NN) {
            int r = g_rowptr[idx] + boff;
            g_rowptr[idx] = r;
            g_head[idx] = r;
        }
    }
    if (blockIdx.x == 0 && t == 0) g_rowptr[NN] = NE;
}

__global__ void k_fill(const void* __restrict__ ei) {
    int e = blockIdx.x * blockDim.x + threadIdx.x;
    if (e >= NE) return;
    int s, d;
    edge_pair(ei, e, s, d);
    int pos = atomicAdd(&g_head[d], 1);
    g_csr[pos] = make_int2(s, __float_as_int(g_dinv[s]));
}

// ---------------- GEMM  [N,128] @ [128,128]  (R4 shape, verified) -----------
// 256 threads, 64x128 tile, BK=32, thread micro-tile 8x4.
template<bool BN>
__global__ void k_gemm128_t(const float* __restrict__ X, const float* __restrict__ W,
                            float* __restrict__ H, int nrows) {
    __shared__ float Xs[64][33];
    __shared__ float Ws[32][128];
    int tid = threadIdx.x;
    int ty = tid >> 5;
    int tx = tid & 31;
    int row0 = blockIdx.x * 64;
    float scr[4], shr[4];
    if (BN) {
        #pragma unroll
        for (int k = 0; k < 4; k++) {
            scr[k] = g_bnsc[k * 32 + tx];
            shr[k] = g_bnsh[k * 32 + tx];
        }
    }
    float acc[8][4];
    #pragma unroll
    for (int r = 0; r < 8; r++)
        #pragma unroll
        for (int c = 0; c < 4; c++) acc[r][c] = 0.f;

    #pragma unroll
    for (int kb = 0; kb < 4; kb++) {
        int k0 = kb * 32;
        #pragma unroll
        for (int i = 0; i < 8; i++) {
            int rr = ty + i * 8;
            int grow = row0 + rr;
            float v = (grow < nrows) ? X[(size_t)grow * 128 + k0 + tx] : 0.f;
            if (BN) v = fmaxf(0.f, fmaf(v, scr[kb], shr[kb]));
            Xs[rr][tx] = v;
        }
        {
            int c = tid & 127;
            int kk = tid >> 7;
            #pragma unroll
            for (int i = 0; i < 16; i++) {
                int k = kk + i * 2;
                Ws[k][c] = W[(size_t)(k0 + k) * 128 + c];
            }
        }
        __syncthreads();
        #pragma unroll
        for (int k = 0; k < 32; k++) {
            float4 b = *(const float4*)&Ws[k][tx * 4];
            #pragma unroll
            for (int r = 0; r < 8; r++) {
                float a = Xs[ty * 8 + r][k];
                acc[r][0] = fmaf(a, b.x, acc[r][0]);
                acc[r][1] = fmaf(a, b.y, acc[r][1]);
                acc[r][2] = fmaf(a, b.z, acc[r][2]);
                acc[r][3] = fmaf(a, b.w, acc[r][3]);
            }
        }
        __syncthreads();
    }
    #pragma unroll
    for (int r = 0; r < 8; r++) {
        int grow = row0 + ty * 8 + r;
        if (grow < nrows) {
            float4 o = make_float4(acc[r][0], acc[r][1], acc[r][2], acc[r][3]);
            *(float4*)&H[(size_t)grow * 128 + tx * 4] = o;
        }
    }
}

// ---------------- GEMM  [N,128] @ [128,40]  (fused BN+ReLU on load) ---------
template<bool BN>
__global__ void k_gemm40_t(const float* __restrict__ X, const float* __restrict__ W,
                           float* __restrict__ H) {
    __shared__ float Ws[128][64];
    int tid = threadIdx.x;
    for (int i = tid; i < 128 * 64; i += 256) {
        int k = i >> 6, c = i & 63;
        Ws[k][c] = (c < DO) ? W[k * DO + c] : 0.f;
    }
    __syncthreads();
    int warp = tid >> 5, lane = tid & 31;
    float scr[4], shr[4];
    if (BN) {
        #pragma unroll
        for (int j = 0; j < 4; j++) {
            scr[j] = g_bnsc[lane + 32 * j];
            shr[j] = g_bnsh[lane + 32 * j];
        }
    }
    for (int row = blockIdx.x * 8 + warp; row < NN; row += gridDim.x * 8) {
        const float* x = X + (size_t)row * 128;
        float xr[4];
        #pragma unroll
        for (int j = 0; j < 4; j++) {
            float v = x[lane + 32 * j];
            if (BN) v = fmaxf(0.f, fmaf(v, scr[j], shr[j]));
            xr[j] = v;
        }
        float acc0 = 0.f, acc1 = 0.f;
        #pragma unroll
        for (int j = 0; j < 4; j++) {
            #pragma unroll
            for (int k = 0; k < 32; k++) {
                float xk = __shfl_sync(0xffffffffu, xr[j], k);
                int kk = j * 32 + k;
                acc0 = fmaf(xk, Ws[kk][lane], acc0);
                acc1 = fmaf(xk, Ws[kk][32 + lane], acc1);
            }
        }
        H[(size_t)row * DO + lane] = acc0;
        if (lane < 8) H[(size_t)row * DO + 32 + lane] = acc1;
    }
}

// ---------------- pull aggregation (R4 warp-per-node) + fused BN stats -------
// 12500 blocks x 8 warps, exactly one node per warp (100000 = 12500*8).
__global__ void __launch_bounds__(256) k_pull128s(const float* __restrict__ H,
                                                  float* __restrict__ A) {
    int tid = threadIdx.x;
    int warp = tid >> 5, lane = tid & 31;
    int node = blockIdx.x * 8 + warp;
    int beg = g_rowptr[node], end = g_rowptr[node + 1];
    float di = g_dinv[node];
    float4 hn = ((const float4*)(H + (size_t)node * 128))[lane];
    float4 acc = make_float4(hn.x * di, hn.y * di, hn.z * di, hn.w * di);
    int p = beg;
    for (; p + 1 < end; p += 2) {
        int2 e0 = __ldg(&g_csr[p]);
        int2 e1 = __ldg(&g_csr[p + 1]);
        float4 v0 = ((const float4*)(H + (size_t)e0.x * 128))[lane];
        float4 v1 = ((const float4*)(H + (size_t)e1.x * 128))[lane];
        float w0 = __int_as_float(e0.y);
        float w1 = __int_as_float(e1.y);
        acc.x = fmaf(v0.x, w0, acc.x); acc.y = fmaf(v0.y, w0, acc.y);
        acc.z = fmaf(v0.z, w0, acc.z); acc.w = fmaf(v0.w, w0, acc.w);
        acc.x = fmaf(v1.x, w1, acc.x); acc.y = fmaf(v1.y, w1, acc.y);
        acc.z = fmaf(v1.z, w1, acc.z); acc.w = fmaf(v1.w, w1, acc.w);
    }
    if (p < end) {
        int2 e0 = __ldg(&g_csr[p]);
        float4 v0 = ((const float4*)(H + (size_t)e0.x * 128))[lane];
        float w0 = __int_as_float(e0.y);
        acc.x = fmaf(v0.x, w0, acc.x); acc.y = fmaf(v0.y, w0, acc.y);
        acc.z = fmaf(v0.z, w0, acc.z); acc.w = fmaf(v0.w, w0, acc.w);
    }
    float4 o = make_float4(acc.x * di, acc.y * di, acc.z * di, acc.w * di);
    ((float4*)(A + (size_t)node * 128))[lane] = o;

    // fused BN stats: block reduce over 8 warps, then atomics to 128 cols
    __shared__ float4 s_cs[8][32];
    __shared__ float4 s_cq[8][32];
    s_cs[warp][lane] = o;
    s_cq[warp][lane] = make_float4(o.x * o.x, o.y * o.y, o.z * o.z, o.w * o.w);
    __syncthreads();
    if (warp == 0) {
        float4 t = s_cs[0][lane];
        #pragma unroll
        for (int w = 1; w < 8; w++) {
            float4 u = s_cs[w][lane];
            t.x += u.x; t.y += u.y; t.z += u.z; t.w += u.w;
        }
        atomicAdd(&g_cs[lane * 4 + 0], t.x);
        atomicAdd(&g_cs[lane * 4 + 1], t.y);
        atomicAdd(&g_cs[lane * 4 + 2], t.z);
        atomicAdd(&g_cs[lane * 4 + 3], t.w);
    } else if (warp == 1) {
        float4 t = s_cq[0][lane];
        #pragma unroll
        for (int w = 1; w < 8; w++) {
            float4 u = s_cq[w][lane];
            t.x += u.x; t.y += u.y; t.z += u.z; t.w += u.w;
        }
        atomicAdd(&g_cs2[lane * 4 + 0], t.x);
        atomicAdd(&g_cs2[lane * 4 + 1], t.y);
        atomicAdd(&g_cs2[lane * 4 + 2], t.z);
        atomicAdd(&g_cs2[lane * 4 + 3], t.w);
    }
}

// ---------------- pull40 + bias + log_softmax fused --------------------------
__global__ void k_pull40lsm(const float* __restrict__ H, float* __restrict__ O,
                            const float* __restrict__ bf) {
    int node = (blockIdx.x * blockDim.x + threadIdx.x) >> 5;
    int lane = threadIdx.x & 31;
    if (node >= NN) return;
    bool act = lane < 20;
    int beg = g_rowptr[node], end = g_rowptr[node + 1];
    float di = g_dinv[node];
    float2 acc = make_float2(0.f, 0.f);
    if (act) {
        float2 hn = ((const float2*)(H + (size_t)node * DO))[lane];
        acc = make_float2(hn.x * di, hn.y * di);
    }
    for (int p = beg; p < end; p++) {
        int2 e0 = __ldg(&g_csr[p]);
        if (act) {
            float2 v = ((const float2*)(H + (size_t)e0.x * DO))[lane];
            float w = __int_as_float(e0.y);
            acc.x = fmaf(v.x, w, acc.x);
            acc.y = fmaf(v.y, w, acc.y);
        }
    }
    float z0 = -1e30f, z1 = -1e30f;
    if (act) {
        z0 = acc.x * di + bf[2 * lane];
        z1 = acc.y * di + bf[2 * lane + 1];
    }
    float m = fmaxf(z0, z1);
    #pragma unroll
    for (int o = 16; o; o >>= 1) m = fmaxf(m, __shfl_xor_sync(0xffffffffu, m, o));
    float s = act ? (expf(z0 - m) + expf(z1 - m)) : 0.f;
    #pragma unroll
    for (int o = 16; o; o >>= 1) s += __shfl_xor_sync(0xffffffffu, s, o);
    float l = m + logf(s);
    if (act)
        ((float2*)(O + (size_t)node * DO))[lane] = make_float2(z0 - l, z1 - l);
}

// ---------------- BN prep ----------------------------------------------------
__global__ void k_bnprep(const float* __restrict__ gamma, const float* __restrict__ beta) {
    int t = threadIdx.x;   // 128 threads
    float mu  = g_cs[t]  * (1.0f / NN);
    float var = g_cs2[t] * (1.0f / NN) - mu * mu;
    float sc = rsqrtf(var + EPSB) * gamma[t];
    g_bnsc[t] = sc;
    g_bnsh[t] = beta[t] - mu * sc;
    g_cs[t] = 0.f;
    g_cs2[t] = 0.f;
}

// ---------------- launch ----------------------------------------------------
extern "C" void kernel_launch(void* const* d_in, const int* in_sizes, int n_in,
                              void* d_out, int out_size) {
    const float* x  = (const float*)d_in[0];
    const void*  ei = d_in[1];
    const float* W1 = (const float*)d_in[2];
    const float* g1 = (const float*)d_in[4];
    const float* be1 = (const float*)d_in[5];
    const float* W2 = (const float*)d_in[6];
    const float* g2 = (const float*)d_in[8];
    const float* be2 = (const float*)d_in[9];
    const float* Wf = (const float*)d_in[10];
    const float* bf = (const float*)d_in[11];
    float* out = (float*)d_out;

    float *H, *A, *H40;
    cudaGetSymbolAddress((void**)&H,   g_H);
    cudaGetSymbolAddress((void**)&A,   g_A);
    cudaGetSymbolAddress((void**)&H40, g_H40);

    const int TB = 256;
    const int gN  = (NN + TB - 1) / TB;
    const int gE  = (NE + TB - 1) / TB;
    const int gW  = (NN * 32 + TB - 1) / TB;   // 12500: warp per node
    const int gGe = (NN + 63) / 64;

    // ---- CSR build
    k_detect<<<1, 32>>>((const long long*)ei);
    k_zero<<<gN, TB>>>();
    k_count<<<gE, TB>>>(ei);
    k_scan1<<<NB_SCAN, TB>>>();                // also computes dinv
    k_scan2<<<1, 128>>>();
    k_scan3<<<NB_SCAN, TB>>>();
    k_fill<<<gE, TB>>>(ei);

    // ---- layer 1
    k_gemm128_t<false><<<gGe, TB>>>(x, W1, H, NN);
    k_pull128s<<<gW, TB>>>(H, A);
    k_bnprep<<<1, 128>>>(g1, be1);

    // ---- layer 2 (BN+ReLU fused into GEMM load)
    k_gemm128_t<true><<<gGe, TB>>>(A, W2, H, NN);
    k_pull128s<<<gW, TB>>>(H, A);
    k_bnprep<<<1, 128>>>(g2, be2);

    // ---- final layer
    k_gemm40_t<true><<<2048, TB>>>(A, Wf, H40);
    k_pull40lsm<<<gW, TB>>>(H40, out, bf);
}

// round 10
// speedup vs baseline: 1.6642x; 1.6642x over previous
#include <cuda_runtime.h>
#include <cstdint>

#define NN   100000
#define NE   1600000
#define DH   128
#define DO   40
#define EPSB 1e-5f
#define NB_SCAN 98            // ceil(NN/1024)

// ---------------- scratch (static device globals; no allocations) ----------
__device__ float g_H  [(size_t)NN * DH];
__device__ float g_A  [(size_t)NN * DH];
__device__ float g_H40[(size_t)NN * DO];
__device__ float g_dinv[NN];
__device__ int   g_cnt [NN];
__device__ int   g_rowptr[NN + 1];
__device__ int   g_head[NN];
__device__ int   g_bsum[128];
__device__ int2  g_csr[NE];
// BN stat accumulators PADDED to 128B stride: col c lives at [c*32] -> its own
// cache line -> atomics spread across all LTS slices instead of 4 lines.
__device__ float g_csP [DH * 32];
__device__ float g_cs2P[DH * 32];
__device__ float g_bnsc[DH];
__device__ float g_bnsh[DH];
__device__ int   g_is64;

// ---------------- helpers ---------------------------------------------------
__device__ __forceinline__ void edge_pair(const void* ei, int e, int& s, int& d) {
    if (g_is64) {
        const long long* p = (const long long*)ei;
        s = (int)__ldg(p + e);
        d = (int)__ldg(p + NE + e);
    } else {
        const int* p = (const int*)ei;
        s = __ldg(p + e);
        d = __ldg(p + NE + e);
    }
}

// ---------------- dtype detection ------------------------------------------
__global__ void k_detect(const long long* __restrict__ p) {
    if (blockIdx.x == 0 && threadIdx.x == 0) {
        int ok = 1;
        for (int i = 0; i < 256; i++) {
            long long v = p[i];
            if (v < 0 || v >= NN) { ok = 0; break; }
        }
        g_is64 = ok;
    }
}

// ---------------- CSR build --------------------------------------------------
__global__ void k_zero() {
    int i = blockIdx.x * blockDim.x + threadIdx.x;
    if (i < NN) g_cnt[i] = 0;
    if (i < DH) { g_csP[i * 32] = 0.f; g_cs2P[i * 32] = 0.f; }
}

__global__ void k_count(const void* __restrict__ ei) {
    int e = blockIdx.x * blockDim.x + threadIdx.x;
    if (e >= NE) return;
    int s, d;
    edge_pair(ei, e, s, d);
    atomicAdd(&g_cnt[d], 1);
}

// scan1 also computes dinv (cnt already in registers)
__global__ void k_scan1() {
    __shared__ int wsumsh[8];
    __shared__ int woff[8];
    int t = threadIdx.x, lane = t & 31, w = t >> 5;
    int base = blockIdx.x * 1024 + t * 4;
    int v0 = 0, v1 = 0, v2 = 0, v3 = 0;
    if (base + 3 < NN) {
        int4 c = *(const int4*)&g_cnt[base];
        v0 = c.x; v1 = c.y; v2 = c.z; v3 = c.w;
    } else {
        if (base     < NN) v0 = g_cnt[base];
        if (base + 1 < NN) v1 = g_cnt[base + 1];
        if (base + 2 < NN) v2 = g_cnt[base + 2];
        if (base + 3 < NN) v3 = g_cnt[base + 3];
    }
    if (base     < NN) g_dinv[base]     = rsqrtf((float)v0 + 1.0f);
    if (base + 1 < NN) g_dinv[base + 1] = rsqrtf((float)v1 + 1.0f);
    if (base + 2 < NN) g_dinv[base + 2] = rsqrtf((float)v2 + 1.0f);
    if (base + 3 < NN) g_dinv[base + 3] = rsqrtf((float)v3 + 1.0f);
    int lsum = v0 + v1 + v2 + v3;
    int x = lsum;
    #pragma unroll
    for (int o = 1; o < 32; o <<= 1) {
        int y = __shfl_up_sync(0xffffffffu, x, o);
        if (lane >= o) x += y;
    }
    if (lane == 31) wsumsh[w] = x;
    __syncthreads();
    if (t == 0) {
        int r = 0;
        for (int i = 0; i < 8; i++) { woff[i] = r; r += wsumsh[i]; }
        g_bsum[blockIdx.x] = r;
    }
    __syncthreads();
    int excl = x - lsum + woff[w];
    if (base     < NN) g_rowptr[base]     = excl;
    if (base + 1 < NN) g_rowptr[base + 1] = excl + v0;
    if (base + 2 < NN) g_rowptr[base + 2] = excl + v0 + v1;
    if (base + 3 < NN) g_rowptr[base + 3] = excl + v0 + v1 + v2;
}

__global__ void k_scan2() {
    __shared__ int sh[128];
    int t = threadIdx.x;
    sh[t] = (t < NB_SCAN) ? g_bsum[t] : 0;
    __syncthreads();
    if (t == 0) {
        int r = 0;
        for (int i = 0; i < NB_SCAN; i++) { int c = sh[i]; sh[i] = r; r += c; }
    }
    __syncthreads();
    if (t < NB_SCAN) g_bsum[t] = sh[t];
}

__global__ void k_scan3() {
    int boff = g_bsum[blockIdx.x];
    int t = threadIdx.x;
    int base = blockIdx.x * 1024 + t * 4;
    #pragma unroll
    for (int j = 0; j < 4; j++) {
        int idx = base + j;
        if (idx < NN) {
            int r = g_rowptr[idx] + boff;
            g_rowptr[idx] = r;
            g_head[idx] = r;
        }
    }
    if (blockIdx.x == 0 && t == 0) g_rowptr[NN] = NE;
}

__global__ void k_fill(const void* __restrict__ ei) {
    int e = blockIdx.x * blockDim.x + threadIdx.x;
    if (e >= NE) return;
    int s, d;
    edge_pair(ei, e, s, d);
    int pos = atomicAdd(&g_head[d], 1);
    g_csr[pos] = make_int2(s, __float_as_int(g_dinv[s]));
}

// ---------------- GEMM  [N,128] @ [128,128]  (R4 shape, verified) -----------
// 256 threads, 64x128 tile, BK=32, thread micro-tile 8x4.
template<bool BN>
__global__ void k_gemm128_t(const float* __restrict__ X, const float* __restrict__ W,
                            float* __restrict__ H, int nrows) {
    __shared__ float Xs[64][33];
    __shared__ float Ws[32][128];
    int tid = threadIdx.x;
    int ty = tid >> 5;
    int tx = tid & 31;
    int row0 = blockIdx.x * 64;
    float scr[4], shr[4];
    if (BN) {
        #pragma unroll
        for (int k = 0; k < 4; k++) {
            scr[k] = g_bnsc[k * 32 + tx];
            shr[k] = g_bnsh[k * 32 + tx];
        }
    }
    float acc[8][4];
    #pragma unroll
    for (int r = 0; r < 8; r++)
        #pragma unroll
        for (int c = 0; c < 4; c++) acc[r][c] = 0.f;

    #pragma unroll
    for (int kb = 0; kb < 4; kb++) {
        int k0 = kb * 32;
        #pragma unroll
        for (int i = 0; i < 8; i++) {
            int rr = ty + i * 8;
            int grow = row0 + rr;
            float v = (grow < nrows) ? X[(size_t)grow * 128 + k0 + tx] : 0.f;
            if (BN) v = fmaxf(0.f, fmaf(v, scr[kb], shr[kb]));
            Xs[rr][tx] = v;
        }
        {
            int c = tid & 127;
            int kk = tid >> 7;
            #pragma unroll
            for (int i = 0; i < 16; i++) {
                int k = kk + i * 2;
                Ws[k][c] = W[(size_t)(k0 + k) * 128 + c];
            }
        }
        __syncthreads();
        #pragma unroll
        for (int k = 0; k < 32; k++) {
            float4 b = *(const float4*)&Ws[k][tx * 4];
            #pragma unroll
            for (int r = 0; r < 8; r++) {
                float a = Xs[ty * 8 + r][k];
                acc[r][0] = fmaf(a, b.x, acc[r][0]);
                acc[r][1] = fmaf(a, b.y, acc[r][1]);
                acc[r][2] = fmaf(a, b.z, acc[r][2]);
                acc[r][3] = fmaf(a, b.w, acc[r][3]);
            }
        }
        __syncthreads();
    }
    #pragma unroll
    for (int r = 0; r < 8; r++) {
        int grow = row0 + ty * 8 + r;
        if (grow < nrows) {
            float4 o = make_float4(acc[r][0], acc[r][1], acc[r][2], acc[r][3]);
            *(float4*)&H[(size_t)grow * 128 + tx * 4] = o;
        }
    }
}

// ---------------- GEMM  [N,128] @ [128,40]  (fused BN+ReLU on load) ---------
template<bool BN>
__global__ void k_gemm40_t(const float* __restrict__ X, const float* __restrict__ W,
                           float* __restrict__ H) {
    __shared__ float Ws[128][64];
    int tid = threadIdx.x;
    for (int i = tid; i < 128 * 64; i += 256) {
        int k = i >> 6, c = i & 63;
        Ws[k][c] = (c < DO) ? W[k * DO + c] : 0.f;
    }
    __syncthreads();
    int warp = tid >> 5, lane = tid & 31;
    float scr[4], shr[4];
    if (BN) {
        #pragma unroll
        for (int j = 0; j < 4; j++) {
            scr[j] = g_bnsc[lane + 32 * j];
            shr[j] = g_bnsh[lane + 32 * j];
        }
    }
    for (int row = blockIdx.x * 8 + warp; row < NN; row += gridDim.x * 8) {
        const float* x = X + (size_t)row * 128;
        float xr[4];
        #pragma unroll
        for (int j = 0; j < 4; j++) {
            float v = x[lane + 32 * j];
            if (BN) v = fmaxf(0.f, fmaf(v, scr[j], shr[j]));
            xr[j] = v;
        }
        float acc0 = 0.f, acc1 = 0.f;
        #pragma unroll
        for (int j = 0; j < 4; j++) {
            #pragma unroll
            for (int k = 0; k < 32; k++) {
                float xk = __shfl_sync(0xffffffffu, xr[j], k);
                int kk = j * 32 + k;
                acc0 = fmaf(xk, Ws[kk][lane], acc0);
                acc1 = fmaf(xk, Ws[kk][32 + lane], acc1);
            }
        }
        H[(size_t)row * DO + lane] = acc0;
        if (lane < 8) H[(size_t)row * DO + 32 + lane] = acc1;
    }
}

// ---------------- pull aggregation (R4 warp-per-node) + fused BN stats -------
// 12500 blocks x 8 warps, exactly one node per warp. Stats atomics go to
// PADDED accumulators (one cache line per column) -> spread across LTS slices.
__global__ void __launch_bounds__(256) k_pull128s(const float* __restrict__ H,
                                                  float* __restrict__ A) {
    int tid = threadIdx.x;
    int warp = tid >> 5, lane = tid & 31;
    int node = blockIdx.x * 8 + warp;
    int beg = g_rowptr[node], end = g_rowptr[node + 1];
    float di = g_dinv[node];
    float4 hn = ((const float4*)(H + (size_t)node * 128))[lane];
    float4 acc = make_float4(hn.x * di, hn.y * di, hn.z * di, hn.w * di);
    int p = beg;
    for (; p + 1 < end; p += 2) {
        int2 e0 = __ldg(&g_csr[p]);
        int2 e1 = __ldg(&g_csr[p + 1]);
        float4 v0 = ((const float4*)(H + (size_t)e0.x * 128))[lane];
        float4 v1 = ((const float4*)(H + (size_t)e1.x * 128))[lane];
        float w0 = __int_as_float(e0.y);
        float w1 = __int_as_float(e1.y);
        acc.x = fmaf(v0.x, w0, acc.x); acc.y = fmaf(v0.y, w0, acc.y);
        acc.z = fmaf(v0.z, w0, acc.z); acc.w = fmaf(v0.w, w0, acc.w);
        acc.x = fmaf(v1.x, w1, acc.x); acc.y = fmaf(v1.y, w1, acc.y);
        acc.z = fmaf(v1.z, w1, acc.z); acc.w = fmaf(v1.w, w1, acc.w);
    }
    if (p < end) {
        int2 e0 = __ldg(&g_csr[p]);
        float4 v0 = ((const float4*)(H + (size_t)e0.x * 128))[lane];
        float w0 = __int_as_float(e0.y);
        acc.x = fmaf(v0.x, w0, acc.x); acc.y = fmaf(v0.y, w0, acc.y);
        acc.z = fmaf(v0.z, w0, acc.z); acc.w = fmaf(v0.w, w0, acc.w);
    }
    float4 o = make_float4(acc.x * di, acc.y * di, acc.z * di, acc.w * di);
    ((float4*)(A + (size_t)node * 128))[lane] = o;

    // fused BN stats: block reduce over 8 warps, then line-padded atomics
    __shared__ float4 s_cs[8][32];
    __shared__ float4 s_cq[8][32];
    s_cs[warp][lane] = o;
    s_cq[warp][lane] = make_float4(o.x * o.x, o.y * o.y, o.z * o.z, o.w * o.w);
    __syncthreads();
    if (warp == 0) {
        float4 t = s_cs[0][lane];
        #pragma unroll
        for (int w = 1; w < 8; w++) {
            float4 u = s_cs[w][lane];
            t.x += u.x; t.y += u.y; t.z += u.z; t.w += u.w;
        }
        atomicAdd(&g_csP[(lane * 4 + 0) * 32], t.x);
        atomicAdd(&g_csP[(lane * 4 + 1) * 32], t.y);
        atomicAdd(&g_csP[(lane * 4 + 2) * 32], t.z);
        atomicAdd(&g_csP[(lane * 4 + 3) * 32], t.w);
    } else if (warp == 1) {
        float4 t = s_cq[0][lane];
        #pragma unroll
        for (int w = 1; w < 8; w++) {
            float4 u = s_cq[w][lane];
            t.x += u.x; t.y += u.y; t.z += u.z; t.w += u.w;
        }
        atomicAdd(&g_cs2P[(lane * 4 + 0) * 32], t.x);
        atomicAdd(&g_cs2P[(lane * 4 + 1) * 32], t.y);
        atomicAdd(&g_cs2P[(lane * 4 + 2) * 32], t.z);
        atomicAdd(&g_cs2P[(lane * 4 + 3) * 32], t.w);
    }
}

// ---------------- pull40 + bias + log_softmax fused --------------------------
__global__ void k_pull40lsm(const float* __restrict__ H, float* __restrict__ O,
                            const float* __restrict__ bf) {
    int node = (blockIdx.x * blockDim.x + threadIdx.x) >> 5;
    int lane = threadIdx.x & 31;
    if (node >= NN) return;
    bool act = lane < 20;
    int beg = g_rowptr[node], end = g_rowptr[node + 1];
    float di = g_dinv[node];
    float2 acc = make_float2(0.f, 0.f);
    if (act) {
        float2 hn = ((const float2*)(H + (size_t)node * DO))[lane];
        acc = make_float2(hn.x * di, hn.y * di);
    }
    for (int p = beg; p < end; p++) {
        int2 e0 = __ldg(&g_csr[p]);
        if (act) {
            float2 v = ((const float2*)(H + (size_t)e0.x * DO))[lane];
            float w = __int_as_float(e0.y);
            acc.x = fmaf(v.x, w, acc.x);
            acc.y = fmaf(v.y, w, acc.y);
        }
    }
    float z0 = -1e30f, z1 = -1e30f;
    if (act) {
        z0 = acc.x * di + bf[2 * lane];
        z1 = acc.y * di + bf[2 * lane + 1];
    }
    float m = fmaxf(z0, z1);
    #pragma unroll
    for (int o = 16; o; o >>= 1) m = fmaxf(m, __shfl_xor_sync(0xffffffffu, m, o));
    float s = act ? (expf(z0 - m) + expf(z1 - m)) : 0.f;
    #pragma unroll
    for (int o = 16; o; o >>= 1) s += __shfl_xor_sync(0xffffffffu, s, o);
    float l = m + logf(s);
    if (act)
        ((float2*)(O + (size_t)node * DO))[lane] = make_float2(z0 - l, z1 - l);
}

// ---------------- BN prep (reads padded accumulators) ------------------------
__global__ void k_bnprep(const float* __restrict__ gamma, const float* __restrict__ beta) {
    int t = threadIdx.x;   // 128 threads
    float mu  = g_csP[t * 32]  * (1.0f / NN);
    float var = g_cs2P[t * 32] * (1.0f / NN) - mu * mu;
    float sc = rsqrtf(var + EPSB) * gamma[t];
    g_bnsc[t] = sc;
    g_bnsh[t] = beta[t] - mu * sc;
    g_csP[t * 32] = 0.f;
    g_cs2P[t * 32] = 0.f;
}

// ---------------- launch ----------------------------------------------------
extern "C" void kernel_launch(void* const* d_in, const int* in_sizes, int n_in,
                              void* d_out, int out_size) {
    const float* x  = (const float*)d_in[0];
    const void*  ei = d_in[1];
    const float* W1 = (const float*)d_in[2];
    const float* g1 = (const float*)d_in[4];
    const float* be1 = (const float*)d_in[5];
    const float* W2 = (const float*)d_in[6];
    const float* g2 = (const float*)d_in[8];
    const float* be2 = (const float*)d_in[9];
    const float* Wf = (const float*)d_in[10];
    const float* bf = (const float*)d_in[11];
    float* out = (float*)d_out;

    float *H, *A, *H40;
    cudaGetSymbolAddress((void**)&H,   g_H);
    cudaGetSymbolAddress((void**)&A,   g_A);
    cudaGetSymbolAddress((void**)&H40, g_H40);

    const int TB = 256;
    const int gN  = (NN + TB - 1) / TB;
    const int gE  = (NE + TB - 1) / TB;
    const int gW  = (NN * 32 + TB - 1) / TB;   // 12500: warp per node
    const int gGe = (NN + 63) / 64;

    // ---- CSR build
    k_detect<<<1, 32>>>((const long long*)ei);
    k_zero<<<gN, TB>>>();
    k_count<<<gE, TB>>>(ei);
    k_scan1<<<NB_SCAN, TB>>>();                // also computes dinv
    k_scan2<<<1, 128>>>();
    k_scan3<<<NB_SCAN, TB>>>();
    k_fill<<<gE, TB>>>(ei);

    // ---- layer 1
    k_gemm128_t<false><<<gGe, TB>>>(x, W1, H, NN);
    k_pull128s<<<gW, TB>>>(H, A);
    k_bnprep<<<1, 128>>>(g1, be1);

    // ---- layer 2 (BN+ReLU fused into GEMM load)
    k_gemm128_t<true><<<gGe, TB>>>(A, W2, H, NN);
    k_pull128s<<<gW, TB>>>(H, A);
    k_bnprep<<<1, 128>>>(g2, be2);

    // ---- final layer
    k_gemm40_t<true><<<2048, TB>>>(A, Wf, H40);
    k_pull40lsm<<<gW, TB>>>(H40, out, bf);
}